// round 16
// baseline (speedup 1.0000x reference)
#include <cuda_runtime.h>

// Problem dims (fixed for SNN_Vanilla_11630771437863)
#define BB 256      // batch
#define TT 100      // timesteps
#define DD 2312     // input dim (2*34*34)
#define HH 1000     // hidden
#define OO 10       // output

typedef unsigned long long ull;

// Scratch: cur1_all stored [B][T][H] (b-major so scan CTA b reads contiguously)
__device__ float g_cur1[(size_t)BB * TT * HH];   // 102.4 MB

// Packed f32x2 helpers (sm_103a). fma.rn.f32x2 / add.rn.f32x2 are two
// INDEPENDENT IEEE-754 rn fp32 ops per instruction -> bitwise identical to
// two scalar fmaf/__fadd_rn. Numerics of the frozen Eigen order preserved.
__device__ __forceinline__ ull fma2(ull a, ull b, ull c) {
    ull d;
    asm("fma.rn.f32x2 %0, %1, %2, %3;" : "=l"(d) : "l"(a), "l"(b), "l"(c));
    return d;
}
__device__ __forceinline__ ull add2(ull a, ull b) {
    ull d;
    asm("add.rn.f32x2 %0, %1, %2;" : "=l"(d) : "l"(a), "l"(b));
    return d;
}
__device__ __forceinline__ float lo32(ull v) { return __uint_as_float((unsigned)v); }
__device__ __forceinline__ float hi32(ull v) { return __uint_as_float((unsigned)(v >> 32)); }

// ---------------------------------------------------------------------------
// Kernel 1 (NUMERICS FROZEN — R8 passing Eigen order, bitwise preserved):
// cur1[r][n] = sum_k A[r][k] * W1[n][k] + b1[n]
// Eigen ST gebp: balanced kc = 232; panels 9 x 232 + 224; ascending-k
// single-accumulator chain per panel; panels summed sequentially; one fp32
// bias add. FFMA2-packed over M pairs.
//
// R15 structure (BK=16, single small loop body). One change vs R15: Bs holds
// PRE-DUPLICATED pairs in a transpose-swizzled layout — column n's pair
// (W[n,k], W[n,k]) lives at float offset q(n) = 32*(n&3) + 2*(n>>2) of row k.
// Reader: thread column tn+j = 4i+j -> offset 32j+2i -> banks 2i,2i+1 over
// i=0..15: ALL 32 banks, conflict-free (R12's naive pair layout was 4-way
// conflicted). Writer: 512B/row = 4 crossbar phases = theoretical minimum.
// Removes all 8 dup MOVs per kk; b feeds fma2 directly via LDS.64.
// Same values, same FMA order -> bit-identical.
// ---------------------------------------------------------------------------
__global__ __launch_bounds__(256) void gemm1_kernel(
    const float* __restrict__ A,
    const float* __restrict__ W,
    const float* __restrict__ b1)
{
    __shared__ __align__(16) float As[2][16][128];  // 16 KB
    __shared__ __align__(16) float Bs[2][16][128];  // 16 KB (duplicated pairs)

    const int bm = blockIdx.y;          // 0..199
    const int bn = blockIdx.x;          // 0..15
    const int tid = threadIdx.x;

    const int tm = (tid >> 4) * 8;      // M offset in tile (multiple of 8)
    const int ti = tid & 15;            // N group index (tn = 4*ti)

    const int a_row = tid >> 1;         // 0..127
    const int a_k4  = (tid & 1) * 4;    // 0 or 4
    const int w_row = tid >> 2;         // 0..63  (column n this thread loads)
    const int w_k4  = (tid & 3) * 4;    // 0,4,8,12
    const int nbase = bn * 64;
    const int wn    = nbase + w_row;    // W row this thread loads
    const int wq    = 32 * (w_row & 3) + 2 * (w_row >> 2);   // q(n) writer offset
    const int rq    = 2 * ti;           // reader base: b2[j] at rq + 32*j

    const float* Ar = A + (size_t)(bm * 128 + a_row) * DD;
    const float* Wr = W + (size_t)wn * DD;

    ull tot2[4][4];   // running sum over panels, rows (2p,2p+1) x col j
    ull acc2[4][4];   // current panel partial
#pragma unroll
    for (int p = 0; p < 4; p++)
#pragma unroll
        for (int j = 0; j < 4; j++) { tot2[p][j] = 0ull; acc2[p][j] = 0ull; }

    // prologue: load k-tile 0 (k=0..15) into buffer 0
    {
        float4 av0 = *(const float4*)(Ar + a_k4);
        float4 av1 = *(const float4*)(Ar + 8 + a_k4);
        As[0][a_k4 + 0][a_row] = av0.x;
        As[0][a_k4 + 1][a_row] = av0.y;
        As[0][a_k4 + 2][a_row] = av0.z;
        As[0][a_k4 + 3][a_row] = av0.w;
        As[0][8 + a_k4 + 0][a_row] = av1.x;
        As[0][8 + a_k4 + 1][a_row] = av1.y;
        As[0][8 + a_k4 + 2][a_row] = av1.z;
        As[0][8 + a_k4 + 3][a_row] = av1.w;
        float4 bv = make_float4(0.f, 0.f, 0.f, 0.f);
        if (wn < HH) bv = *(const float4*)(Wr + w_k4);
        *(float2*)&Bs[0][w_k4 + 0][wq] = make_float2(bv.x, bv.x);
        *(float2*)&Bs[0][w_k4 + 1][wq] = make_float2(bv.y, bv.y);
        *(float2*)&Bs[0][w_k4 + 2][wq] = make_float2(bv.z, bv.z);
        *(float2*)&Bs[0][w_k4 + 3][wq] = make_float2(bv.w, bv.w);
    }
    __syncthreads();

    const int NT = 145;     // 144 full 16-wide tiles + 1 half tile
    int buf = 0;
    int pc = 0;             // kt % 29 maintained incrementally
    for (int kt = 0; kt < NT; ++kt) {
        const int nb = buf ^ 1;
        float4 av0, av1, bv;
        const bool have_next = (kt + 1 < NT);
        if (have_next) {
            const int k0 = (kt + 1) * 16;
            av0 = *(const float4*)(Ar + k0 + a_k4);     // always in-bounds (<=2311)
            av1 = make_float4(0.f, 0.f, 0.f, 0.f);
            if (k0 + 16 <= DD)                          // hi half valid?
                av1 = *(const float4*)(Ar + k0 + 8 + a_k4);
            bv = make_float4(0.f, 0.f, 0.f, 0.f);
            if (wn < HH && (k0 + w_k4 + 4 <= DD))
                bv = *(const float4*)(Wr + k0 + w_k4);
        }

        // ---- compute kk = 0..7 (k ascending) ----
#pragma unroll
        for (int kk = 0; kk < 8; kk++) {
            ulonglong2 aq0 = *(const ulonglong2*)&As[buf][kk][tm];      // pairs 0,1
            ulonglong2 aq1 = *(const ulonglong2*)&As[buf][kk][tm + 4];  // pairs 2,3
            ull b2[4];
#pragma unroll
            for (int j = 0; j < 4; j++)
                b2[j] = *(const ull*)&Bs[buf][kk][rq + 32 * j];
#pragma unroll
            for (int j = 0; j < 4; j++) acc2[0][j] = fma2(aq0.x, b2[j], acc2[0][j]);
#pragma unroll
            for (int j = 0; j < 4; j++) acc2[1][j] = fma2(aq0.y, b2[j], acc2[1][j]);
#pragma unroll
            for (int j = 0; j < 4; j++) acc2[2][j] = fma2(aq1.x, b2[j], acc2[2][j]);
#pragma unroll
            for (int j = 0; j < 4; j++) acc2[3][j] = fma2(aq1.y, b2[j], acc2[3][j]);
        }

        // mid-tile panel boundary (k = 232m, m odd): kt = 14,43,72,101,130
        if (pc == 14) {
#pragma unroll
            for (int p = 0; p < 4; p++)
#pragma unroll
                for (int j = 0; j < 4; j++) {
                    tot2[p][j] = add2(tot2[p][j], acc2[p][j]);
                    acc2[p][j] = 0ull;
                }
        }

        // ---- compute kk = 8..15 ----
#pragma unroll
        for (int kk = 8; kk < 16; kk++) {
            ulonglong2 aq0 = *(const ulonglong2*)&As[buf][kk][tm];
            ulonglong2 aq1 = *(const ulonglong2*)&As[buf][kk][tm + 4];
            ull b2[4];
#pragma unroll
            for (int j = 0; j < 4; j++)
                b2[j] = *(const ull*)&Bs[buf][kk][rq + 32 * j];
#pragma unroll
            for (int j = 0; j < 4; j++) acc2[0][j] = fma2(aq0.x, b2[j], acc2[0][j]);
#pragma unroll
            for (int j = 0; j < 4; j++) acc2[1][j] = fma2(aq0.y, b2[j], acc2[1][j]);
#pragma unroll
            for (int j = 0; j < 4; j++) acc2[2][j] = fma2(aq1.x, b2[j], acc2[2][j]);
#pragma unroll
            for (int j = 0; j < 4; j++) acc2[3][j] = fma2(aq1.y, b2[j], acc2[3][j]);
        }

        // end-of-tile panel boundary (k = 232m, m even): kt = 28,57,86,115
        // (NOT the tail tile kt=144, whose 144%29==28 is spurious)
        if (pc == 28 && kt != 144) {
#pragma unroll
            for (int p = 0; p < 4; p++)
#pragma unroll
                for (int j = 0; j < 4; j++) {
                    tot2[p][j] = add2(tot2[p][j], acc2[p][j]);
                    acc2[p][j] = 0ull;
                }
        }

        if (have_next) {
            As[nb][a_k4 + 0][a_row] = av0.x;
            As[nb][a_k4 + 1][a_row] = av0.y;
            As[nb][a_k4 + 2][a_row] = av0.z;
            As[nb][a_k4 + 3][a_row] = av0.w;
            As[nb][8 + a_k4 + 0][a_row] = av1.x;
            As[nb][8 + a_k4 + 1][a_row] = av1.y;
            As[nb][8 + a_k4 + 2][a_row] = av1.z;
            As[nb][8 + a_k4 + 3][a_row] = av1.w;
            *(float2*)&Bs[nb][w_k4 + 0][wq] = make_float2(bv.x, bv.x);
            *(float2*)&Bs[nb][w_k4 + 1][wq] = make_float2(bv.y, bv.y);
            *(float2*)&Bs[nb][w_k4 + 2][wq] = make_float2(bv.z, bv.z);
            *(float2*)&Bs[nb][w_k4 + 3][wq] = make_float2(bv.w, bv.w);
        }
        __syncthreads();
        buf = nb;
        if (++pc == 29) pc = 0;
    }

    // epilogue: flush final (224-wide) panel, add bias once, store.
    // Same op order as R8: fl(fl(tot + acc) + bias), per element.
    const int col = nbase + ti * 4;
    if (col < HH) {
        float4 bias = *(const float4*)(b1 + col);
#pragma unroll
        for (int p = 0; p < 4; p++) {
            float4 vlo, vhi;
            {
                float t0 = __fadd_rn(lo32(tot2[p][0]), lo32(acc2[p][0]));
                float t1 = __fadd_rn(lo32(tot2[p][1]), lo32(acc2[p][1]));
                float t2 = __fadd_rn(lo32(tot2[p][2]), lo32(acc2[p][2]));
                float t3 = __fadd_rn(lo32(tot2[p][3]), lo32(acc2[p][3]));
                vlo.x = __fadd_rn(t0, bias.x);
                vlo.y = __fadd_rn(t1, bias.y);
                vlo.z = __fadd_rn(t2, bias.z);
                vlo.w = __fadd_rn(t3, bias.w);
            }
            {
                float t0 = __fadd_rn(hi32(tot2[p][0]), hi32(acc2[p][0]));
                float t1 = __fadd_rn(hi32(tot2[p][1]), hi32(acc2[p][1]));
                float t2 = __fadd_rn(hi32(tot2[p][2]), hi32(acc2[p][2]));
                float t3 = __fadd_rn(hi32(tot2[p][3]), hi32(acc2[p][3]));
                vhi.x = __fadd_rn(t0, bias.x);
                vhi.y = __fadd_rn(t1, bias.y);
                vhi.z = __fadd_rn(t2, bias.z);
                vhi.w = __fadd_rn(t3, bias.w);
            }
            int rlo = bm * 128 + tm + 2 * p;
            *(float4*)(g_cur1 + (size_t)rlo * HH + col) = vlo;
            *(float4*)(g_cur1 + (size_t)(rlo + 1) * HH + col) = vhi;
        }
    }
}

// ---------------------------------------------------------------------------
// Kernel 2: per-batch temporal scan (R14 version, 71us — keep).
// Recurrence bits FROZEN (rn mul/add/sub):
//   mem = fl( fl( fl(beta*mem) + cur ) - spk )
// Depth-2 prefetch: two register buffers; loads for t+2 issue before the
// reduction of step t.
// ---------------------------------------------------------------------------
__global__ __launch_bounds__(256) void scan_kernel(
    const float* __restrict__ w2,
    const float* __restrict__ b2,
    const float* __restrict__ betap,
    float* __restrict__ out)
{
    const int b   = blockIdx.x;
    const int tid = threadIdx.x;
    const int warp = tid >> 5;
    const int lane = tid & 31;
    const float beta = *betap;

    __shared__ float red[8][16];   // 8 warps x 10 partials (padded)

    // register-resident w2 slices for this thread's h values
    float w2r[4][OO];
#pragma unroll
    for (int j = 0; j < 4; j++) {
        int h = tid + j * 256;
        bool v = (h < HH);
#pragma unroll
        for (int o = 0; o < OO; o++)
            w2r[j][o] = v ? w2[o * HH + h] : 0.f;
    }

    float mem1[4] = {0.f, 0.f, 0.f, 0.f};
    float spk1[4] = {0.f, 0.f, 0.f, 0.f};
    float mem2 = 0.f, spk2 = 0.f;          // meaningful for tid < 10
    float myb2 = (tid < OO) ? b2[tid] : 0.f;

    const float* cur1b = g_cur1 + (size_t)b * TT * HH;

    // depth-2 prefetch buffers
    float curA[4], curB[4];
#pragma unroll
    for (int j = 0; j < 4; j++) {
        int h = tid + j * 256;
        curA[j] = (h < HH) ? __ldg(cur1b + h) : 0.f;
        curB[j] = (h < HH) ? __ldg(cur1b + HH + h) : 0.f;
    }

    auto step = [&](float* cur, int t) {
        float part[OO];
#pragma unroll
        for (int o = 0; o < OO; o++) part[o] = 0.f;

#pragma unroll
        for (int j = 0; j < 4; j++) {
            // mem = fl(fl(fl(beta*mem) + cur) - spk)   (frozen rn op order)
            float m = __fsub_rn(__fadd_rn(__fmul_rn(beta, mem1[j]), cur[j]), spk1[j]);
            mem1[j] = m;
            float s = (m > 1.0f) ? 1.f : 0.f;   // (mem-1)>0 <=> mem>1 (exact)
            spk1[j] = s;
#pragma unroll
            for (int o = 0; o < OO; o++)
                part[o] = fmaf(s, w2r[j][o], part[o]);   // products exact
        }

        // prefetch t+2 into this buffer (consumed two reductions from now)
        if (t + 2 < TT) {
            const float* cn = cur1b + (t + 2) * HH;
#pragma unroll
            for (int j = 0; j < 4; j++) {
                int h = tid + j * 256;
                cur[j] = (h < HH) ? __ldg(cn + h) : 0.f;
            }
        }

        // intra-warp tree reduction (10 independent shuffle chains)
#pragma unroll
        for (int off = 16; off > 0; off >>= 1) {
#pragma unroll
            for (int o = 0; o < OO; o++)
                part[o] += __shfl_xor_sync(0xffffffffu, part[o], off);
        }
        if (lane == 0) {
#pragma unroll
            for (int o = 0; o < OO; o++) red[warp][o] = part[o];
        }
        __syncthreads();

        if (tid < OO) {
            float cur2 = 0.f;
#pragma unroll
            for (int w = 0; w < 8; w++) cur2 = __fadd_rn(cur2, red[w][tid]);
            cur2 = __fadd_rn(cur2, myb2);
            float m2 = __fsub_rn(__fadd_rn(__fmul_rn(beta, mem2), cur2), spk2);
            mem2 = m2;
            spk2 = (m2 > 1.0f) ? 1.f : 0.f;
            size_t idx = (size_t)(t * BB + b) * OO + tid;
            out[idx] = spk2;                                   // spk_rec
            out[(size_t)TT * BB * OO + idx] = mem2;            // mem_rec
        }
        __syncthreads();   // red[] reused next iteration
    };

    for (int t = 0; t < TT; t += 2) {
        step(curA, t);
        step(curB, t + 1);
    }
}

// ---------------------------------------------------------------------------
extern "C" void kernel_launch(void* const* d_in, const int* in_sizes, int n_in,
                              void* d_out, int out_size)
{
    (void)in_sizes; (void)n_in; (void)out_size;
    const float* data = (const float*)d_in[0];   // [256,100,2,34,34] fp32
    const float* w1   = (const float*)d_in[1];   // [1000,2312]
    const float* b1   = (const float*)d_in[2];   // [1000]
    const float* w2   = (const float*)d_in[3];   // [10,1000]
    const float* b2   = (const float*)d_in[4];   // [10]
    const float* beta = (const float*)d_in[5];   // scalar
    float* out = (float*)d_out;                  // [2,100,256,10]

    dim3 g1(16, 200);   // N tiles x M tiles
    gemm1_kernel<<<g1, 256>>>(data, w1, b1);
    scan_kernel<<<BB, 256>>>(w2, b2, beta, out);
}

// round 17
// speedup vs baseline: 1.8627x; 1.8627x over previous
#include <cuda_runtime.h>

// Problem dims (fixed for SNN_Vanilla_11630771437863)
#define BB 256      // batch
#define TT 100      // timesteps
#define DD 2312     // input dim (2*34*34)
#define HH 1000     // hidden
#define OO 10       // output

typedef unsigned long long ull;

// Scratch: cur1_all stored [B][T][H] (b-major so scan CTA b reads contiguously)
__device__ float g_cur1[(size_t)BB * TT * HH];   // 102.4 MB

// Packed f32x2 helpers (sm_103a). fma.rn.f32x2 / add.rn.f32x2 are two
// INDEPENDENT IEEE-754 rn fp32 ops per instruction -> bitwise identical to
// two scalar fmaf/__fadd_rn. Numerics of the frozen Eigen order preserved.
__device__ __forceinline__ ull fma2(ull a, ull b, ull c) {
    ull d;
    asm("fma.rn.f32x2 %0, %1, %2, %3;" : "=l"(d) : "l"(a), "l"(b), "l"(c));
    return d;
}
__device__ __forceinline__ ull add2(ull a, ull b) {
    ull d;
    asm("add.rn.f32x2 %0, %1, %2;" : "=l"(d) : "l"(a), "l"(b));
    return d;
}
__device__ __forceinline__ ull dup2(float x) {
    ull d;
    unsigned xi = __float_as_uint(x);
    asm("mov.b64 %0, {%1, %1};" : "=l"(d) : "r"(xi));
    return d;
}
__device__ __forceinline__ float lo32(ull v) { return __uint_as_float((unsigned)v); }
__device__ __forceinline__ float hi32(ull v) { return __uint_as_float((unsigned)(v >> 32)); }

// ---------------------------------------------------------------------------
// Kernel 1 (NUMERICS FROZEN — R8 passing Eigen order, bitwise preserved):
// cur1[r][n] = sum_k A[r][k] * W1[n][k] + b1[n]
// Eigen ST gebp: balanced kc = 232; panels 9 x 232 + 224; ascending-k
// single-accumulator chain per panel; panels summed sequentially; one fp32
// bias add. FFMA2-packed over M pairs.
//
// EXACT R15 loop (best: 2663us total; GEMM within ~5-9% of the FFMA2 rt=3
// roofline). b-path: 1 LDS.128 + 4 dup MOVs — the MOVs ride the ALU pipe in
// FFMA2's idle issue slots (R12/R16 proved trading them for extra LDS
// regresses 2x). Two provably-free scraps vs R15:
//   (1) W row pointer clamped to row HH-1 for wn >= HH — those threads'
//       accumulators are finite garbage never stored (col<HH guard).
//   (2) end-flush allowed at kt=144 (zero tail): fl(tot+0)=tot, bit-neutral
//       (empirically proven in R12/R13).
// ---------------------------------------------------------------------------
__global__ __launch_bounds__(256) void gemm1_kernel(
    const float* __restrict__ A,
    const float* __restrict__ W,
    const float* __restrict__ b1)
{
    __shared__ __align__(16) float As[2][16][128];  // 16 KB
    __shared__ __align__(16) float Bs[2][16][64];   //  8 KB

    const int bm = blockIdx.y;          // 0..199
    const int bn = blockIdx.x;          // 0..15
    const int tid = threadIdx.x;

    const int tm = (tid >> 4) * 8;      // M offset in tile (multiple of 8)
    const int tn = (tid & 15) * 4;      // N offset in tile (16B aligned)

    const int a_row = tid >> 1;         // 0..127
    const int a_k4  = (tid & 1) * 4;    // 0 or 4
    const int w_row = tid >> 2;         // 0..63
    const int w_k4  = (tid & 3) * 4;    // 0,4,8,12
    const int nbase = bn * 64;
    const int wn    = nbase + w_row;    // W row this thread loads
    const int wnc   = (wn < HH) ? wn : (HH - 1);   // clamped (garbage-safe)

    const float* Ar = A + (size_t)(bm * 128 + a_row) * DD;
    const float* Wr = W + (size_t)wnc * DD;

    ull tot2[4][4];   // running sum over panels, rows (2p,2p+1) x col j
    ull acc2[4][4];   // current panel partial
#pragma unroll
    for (int p = 0; p < 4; p++)
#pragma unroll
        for (int j = 0; j < 4; j++) { tot2[p][j] = 0ull; acc2[p][j] = 0ull; }

    // prologue: load k-tile 0 (k=0..15) into buffer 0
    {
        float4 av0 = *(const float4*)(Ar + a_k4);
        float4 av1 = *(const float4*)(Ar + 8 + a_k4);
        As[0][a_k4 + 0][a_row] = av0.x;
        As[0][a_k4 + 1][a_row] = av0.y;
        As[0][a_k4 + 2][a_row] = av0.z;
        As[0][a_k4 + 3][a_row] = av0.w;
        As[0][8 + a_k4 + 0][a_row] = av1.x;
        As[0][8 + a_k4 + 1][a_row] = av1.y;
        As[0][8 + a_k4 + 2][a_row] = av1.z;
        As[0][8 + a_k4 + 3][a_row] = av1.w;
        float4 bv = *(const float4*)(Wr + w_k4);
        Bs[0][w_k4 + 0][w_row] = bv.x;
        Bs[0][w_k4 + 1][w_row] = bv.y;
        Bs[0][w_k4 + 2][w_row] = bv.z;
        Bs[0][w_k4 + 3][w_row] = bv.w;
    }
    __syncthreads();

    const int NT = 145;     // 144 full 16-wide tiles + 1 half tile
    int buf = 0;
    int pc = 0;             // kt % 29 maintained incrementally
    for (int kt = 0; kt < NT; ++kt) {
        const int nb = buf ^ 1;
        float4 av0, av1, bv;
        const bool have_next = (kt + 1 < NT);
        if (have_next) {
            const int k0 = (kt + 1) * 16;
            av0 = *(const float4*)(Ar + k0 + a_k4);     // always in-bounds (<=2311)
            av1 = make_float4(0.f, 0.f, 0.f, 0.f);
            if (k0 + 16 <= DD)                          // hi half valid?
                av1 = *(const float4*)(Ar + k0 + 8 + a_k4);
            bv = make_float4(0.f, 0.f, 0.f, 0.f);
            if (k0 + w_k4 + 4 <= DD)                    // zero-pad k >= DD
                bv = *(const float4*)(Wr + k0 + w_k4);
        }

        // ---- compute kk = 0..7 (k ascending) ----
#pragma unroll
        for (int kk = 0; kk < 8; kk++) {
            ulonglong2 aq0 = *(const ulonglong2*)&As[buf][kk][tm];      // pairs 0,1
            ulonglong2 aq1 = *(const ulonglong2*)&As[buf][kk][tm + 4];  // pairs 2,3
            float4 bq = *(const float4*)&Bs[buf][kk][tn];
            ull b2[4];
            b2[0] = dup2(bq.x); b2[1] = dup2(bq.y);
            b2[2] = dup2(bq.z); b2[3] = dup2(bq.w);
#pragma unroll
            for (int j = 0; j < 4; j++) acc2[0][j] = fma2(aq0.x, b2[j], acc2[0][j]);
#pragma unroll
            for (int j = 0; j < 4; j++) acc2[1][j] = fma2(aq0.y, b2[j], acc2[1][j]);
#pragma unroll
            for (int j = 0; j < 4; j++) acc2[2][j] = fma2(aq1.x, b2[j], acc2[2][j]);
#pragma unroll
            for (int j = 0; j < 4; j++) acc2[3][j] = fma2(aq1.y, b2[j], acc2[3][j]);
        }

        // mid-tile panel boundary (k = 232m, m odd): kt = 14,43,72,101,130
        if (pc == 14) {
#pragma unroll
            for (int p = 0; p < 4; p++)
#pragma unroll
                for (int j = 0; j < 4; j++) {
                    tot2[p][j] = add2(tot2[p][j], acc2[p][j]);
                    acc2[p][j] = 0ull;
                }
        }

        // ---- compute kk = 8..15 ----
#pragma unroll
        for (int kk = 8; kk < 16; kk++) {
            ulonglong2 aq0 = *(const ulonglong2*)&As[buf][kk][tm];
            ulonglong2 aq1 = *(const ulonglong2*)&As[buf][kk][tm + 4];
            float4 bq = *(const float4*)&Bs[buf][kk][tn];
            ull b2[4];
            b2[0] = dup2(bq.x); b2[1] = dup2(bq.y);
            b2[2] = dup2(bq.z); b2[3] = dup2(bq.w);
#pragma unroll
            for (int j = 0; j < 4; j++) acc2[0][j] = fma2(aq0.x, b2[j], acc2[0][j]);
#pragma unroll
            for (int j = 0; j < 4; j++) acc2[1][j] = fma2(aq0.y, b2[j], acc2[1][j]);
#pragma unroll
            for (int j = 0; j < 4; j++) acc2[2][j] = fma2(aq1.x, b2[j], acc2[2][j]);
#pragma unroll
            for (int j = 0; j < 4; j++) acc2[3][j] = fma2(aq1.y, b2[j], acc2[3][j]);
        }

        // end-of-tile panel boundary (k = 232m, m even): kt = 28,57,86,115.
        // Also fires at kt=144 (zero tail) — bit-neutral: acc is the exact
        // tail partial, fl(tot+acc) now vs in the epilogue is identical.
        if (pc == 28) {
#pragma unroll
            for (int p = 0; p < 4; p++)
#pragma unroll
                for (int j = 0; j < 4; j++) {
                    tot2[p][j] = add2(tot2[p][j], acc2[p][j]);
                    acc2[p][j] = 0ull;
                }
        }

        if (have_next) {
            As[nb][a_k4 + 0][a_row] = av0.x;
            As[nb][a_k4 + 1][a_row] = av0.y;
            As[nb][a_k4 + 2][a_row] = av0.z;
            As[nb][a_k4 + 3][a_row] = av0.w;
            As[nb][8 + a_k4 + 0][a_row] = av1.x;
            As[nb][8 + a_k4 + 1][a_row] = av1.y;
            As[nb][8 + a_k4 + 2][a_row] = av1.z;
            As[nb][8 + a_k4 + 3][a_row] = av1.w;
            Bs[nb][w_k4 + 0][w_row] = bv.x;
            Bs[nb][w_k4 + 1][w_row] = bv.y;
            Bs[nb][w_k4 + 2][w_row] = bv.z;
            Bs[nb][w_k4 + 3][w_row] = bv.w;
        }
        __syncthreads();
        buf = nb;
        if (++pc == 29) pc = 0;
    }

    // epilogue: fold (possibly already-flushed) tail panel, add bias, store.
    // Same op order as R8: fl(fl(tot + acc) + bias), per element.
    const int col = nbase + tn;
    if (col < HH) {
        float4 bias = *(const float4*)(b1 + col);
#pragma unroll
        for (int p = 0; p < 4; p++) {
            float4 vlo, vhi;
            {
                float t0 = __fadd_rn(lo32(tot2[p][0]), lo32(acc2[p][0]));
                float t1 = __fadd_rn(lo32(tot2[p][1]), lo32(acc2[p][1]));
                float t2 = __fadd_rn(lo32(tot2[p][2]), lo32(acc2[p][2]));
                float t3 = __fadd_rn(lo32(tot2[p][3]), lo32(acc2[p][3]));
                vlo.x = __fadd_rn(t0, bias.x);
                vlo.y = __fadd_rn(t1, bias.y);
                vlo.z = __fadd_rn(t2, bias.z);
                vlo.w = __fadd_rn(t3, bias.w);
            }
            {
                float t0 = __fadd_rn(hi32(tot2[p][0]), hi32(acc2[p][0]));
                float t1 = __fadd_rn(hi32(tot2[p][1]), hi32(acc2[p][1]));
                float t2 = __fadd_rn(hi32(tot2[p][2]), hi32(acc2[p][2]));
                float t3 = __fadd_rn(hi32(tot2[p][3]), hi32(acc2[p][3]));
                vhi.x = __fadd_rn(t0, bias.x);
                vhi.y = __fadd_rn(t1, bias.y);
                vhi.z = __fadd_rn(t2, bias.z);
                vhi.w = __fadd_rn(t3, bias.w);
            }
            int rlo = bm * 128 + tm + 2 * p;
            *(float4*)(g_cur1 + (size_t)rlo * HH + col) = vlo;
            *(float4*)(g_cur1 + (size_t)(rlo + 1) * HH + col) = vhi;
        }
    }
}

// ---------------------------------------------------------------------------
// Kernel 2: per-batch temporal scan (R14 version, 71us — keep).
// Recurrence bits FROZEN (rn mul/add/sub):
//   mem = fl( fl( fl(beta*mem) + cur ) - spk )
// Depth-2 prefetch: two register buffers; loads for t+2 issue before the
// reduction of step t.
// ---------------------------------------------------------------------------
__global__ __launch_bounds__(256) void scan_kernel(
    const float* __restrict__ w2,
    const float* __restrict__ b2,
    const float* __restrict__ betap,
    float* __restrict__ out)
{
    const int b   = blockIdx.x;
    const int tid = threadIdx.x;
    const int warp = tid >> 5;
    const int lane = tid & 31;
    const float beta = *betap;

    __shared__ float red[8][16];   // 8 warps x 10 partials (padded)

    // register-resident w2 slices for this thread's h values
    float w2r[4][OO];
#pragma unroll
    for (int j = 0; j < 4; j++) {
        int h = tid + j * 256;
        bool v = (h < HH);
#pragma unroll
        for (int o = 0; o < OO; o++)
            w2r[j][o] = v ? w2[o * HH + h] : 0.f;
    }

    float mem1[4] = {0.f, 0.f, 0.f, 0.f};
    float spk1[4] = {0.f, 0.f, 0.f, 0.f};
    float mem2 = 0.f, spk2 = 0.f;          // meaningful for tid < 10
    float myb2 = (tid < OO) ? b2[tid] : 0.f;

    const float* cur1b = g_cur1 + (size_t)b * TT * HH;

    // depth-2 prefetch buffers
    float curA[4], curB[4];
#pragma unroll
    for (int j = 0; j < 4; j++) {
        int h = tid + j * 256;
        curA[j] = (h < HH) ? __ldg(cur1b + h) : 0.f;
        curB[j] = (h < HH) ? __ldg(cur1b + HH + h) : 0.f;
    }

    auto step = [&](float* cur, int t) {
        float part[OO];
#pragma unroll
        for (int o = 0; o < OO; o++) part[o] = 0.f;

#pragma unroll
        for (int j = 0; j < 4; j++) {
            // mem = fl(fl(fl(beta*mem) + cur) - spk)   (frozen rn op order)
            float m = __fsub_rn(__fadd_rn(__fmul_rn(beta, mem1[j]), cur[j]), spk1[j]);
            mem1[j] = m;
            float s = (m > 1.0f) ? 1.f : 0.f;   // (mem-1)>0 <=> mem>1 (exact)
            spk1[j] = s;
#pragma unroll
            for (int o = 0; o < OO; o++)
                part[o] = fmaf(s, w2r[j][o], part[o]);   // products exact
        }

        // prefetch t+2 into this buffer (consumed two reductions from now)
        if (t + 2 < TT) {
            const float* cn = cur1b + (t + 2) * HH;
#pragma unroll
            for (int j = 0; j < 4; j++) {
                int h = tid + j * 256;
                cur[j] = (h < HH) ? __ldg(cn + h) : 0.f;
            }
        }

        // intra-warp tree reduction (10 independent shuffle chains)
#pragma unroll
        for (int off = 16; off > 0; off >>= 1) {
#pragma unroll
            for (int o = 0; o < OO; o++)
                part[o] += __shfl_xor_sync(0xffffffffu, part[o], off);
        }
        if (lane == 0) {
#pragma unroll
            for (int o = 0; o < OO; o++) red[warp][o] = part[o];
        }
        __syncthreads();

        if (tid < OO) {
            float cur2 = 0.f;
#pragma unroll
            for (int w = 0; w < 8; w++) cur2 = __fadd_rn(cur2, red[w][tid]);
            cur2 = __fadd_rn(cur2, myb2);
            float m2 = __fsub_rn(__fadd_rn(__fmul_rn(beta, mem2), cur2), spk2);
            mem2 = m2;
            spk2 = (m2 > 1.0f) ? 1.f : 0.f;
            size_t idx = (size_t)(t * BB + b) * OO + tid;
            out[idx] = spk2;                                   // spk_rec
            out[(size_t)TT * BB * OO + idx] = mem2;            // mem_rec
        }
        __syncthreads();   // red[] reused next iteration
    };

    for (int t = 0; t < TT; t += 2) {
        step(curA, t);
        step(curB, t + 1);
    }
}

// ---------------------------------------------------------------------------
extern "C" void kernel_launch(void* const* d_in, const int* in_sizes, int n_in,
                              void* d_out, int out_size)
{
    (void)in_sizes; (void)n_in; (void)out_size;
    const float* data = (const float*)d_in[0];   // [256,100,2,34,34] fp32
    const float* w1   = (const float*)d_in[1];   // [1000,2312]
    const float* b1   = (const float*)d_in[2];   // [1000]
    const float* w2   = (const float*)d_in[3];   // [10,1000]
    const float* b2   = (const float*)d_in[4];   // [10]
    const float* beta = (const float*)d_in[5];   // scalar
    float* out = (float*)d_out;                  // [2,100,256,10]

    dim3 g1(16, 200);   // N tiles x M tiles
    gemm1_kernel<<<g1, 256>>>(data, w1, b1);
    scan_kernel<<<BB, 256>>>(w2, b2, beta, out);
}